// round 7
// baseline (speedup 1.0000x reference)
#include <cuda_runtime.h>
#include <cuda_bf16.h>
#include <mma.h>
#include <math.h>
#include <cstdint>

using namespace nvcuda;

#define B_  8
#define T_  1024
#define D_  1024
#define H_  16
#define DH_ 64
#define M_  (B_*T_)     // 8192
#define N3_ (3*D_)      // 3072
#define HALF_D 512

// ---------------- scratch (static device globals) ----------------------------
__device__ __align__(1024) float         g_xn[(size_t)M_*D_];
__device__ __align__(1024) __nv_bfloat16 g_xn_hi[M_*D_];
__device__ __align__(1024) __nv_bfloat16 g_xn_lo[M_*D_];
__device__ __align__(1024) float         g_qkv[(size_t)M_*N3_];
__device__ __align__(1024) float         g_attn[(size_t)M_*D_];
__device__ __align__(1024) __nv_bfloat16 g_at_hi[M_*D_];
__device__ __align__(1024) __nv_bfloat16 g_at_lo[M_*D_];
__device__ __align__(1024) __nv_bfloat16 g_wq_hi[N3_*D_];   // [n][k]
__device__ __align__(1024) __nv_bfloat16 g_wq_lo[N3_*D_];
__device__ __align__(1024) __nv_bfloat16 g_wo_hi[D_*D_];    // [n][k]
__device__ __align__(1024) __nv_bfloat16 g_wo_lo[D_*D_];
__device__ float g_sin [T_*HALF_D];     // [t][pair]  (fp32 fallback layout)
__device__ float g_cos [T_*HALF_D];
__device__ float g_sinT[HALF_D*T_];     // [pair][t]  (MMA epilogue layout)
__device__ float g_cosT[HALF_D*T_];
__device__ int   g_len[B_];
__device__ int   g_flag_q;              // 1 -> wmma qkv wrong, run fp32 fallback
__device__ int   g_flag_o;              // 1 -> wmma out wrong, run fp32 fallback

// ---------------- layernorm -> fp32 + bf16 hi/lo split -------------------------
__global__ void __launch_bounds__(256) ln_kernel(const float* __restrict__ x,
                                                 const float* __restrict__ gamma,
                                                 const float* __restrict__ beta) {
    __shared__ float ssum[8], ssq[8];
    const int row = blockIdx.x;
    const int tid = threadIdx.x;
    float4 v = *(const float4*)(x + (size_t)row * D_ + tid * 4);
    float s = v.x + v.y + v.z + v.w;
    float q = v.x*v.x + v.y*v.y + v.z*v.z + v.w*v.w;
    #pragma unroll
    for (int o = 16; o > 0; o >>= 1) {
        s += __shfl_down_sync(0xffffffffu, s, o);
        q += __shfl_down_sync(0xffffffffu, q, o);
    }
    if ((tid & 31) == 0) { ssum[tid >> 5] = s; ssq[tid >> 5] = q; }
    __syncthreads();
    float ts = 0.f, tq = 0.f;
    #pragma unroll
    for (int i = 0; i < 8; i++) { ts += ssum[i]; tq += ssq[i]; }
    const float mu  = ts * (1.f / 1024.f);
    const float var = tq * (1.f / 1024.f) - mu * mu;
    const float inv = rsqrtf(var + 1e-5f);
    float4 g  = *(const float4*)(gamma + tid * 4);
    float4 be = *(const float4*)(beta  + tid * 4);
    float o0 = (v.x - mu) * inv * g.x + be.x;
    float o1 = (v.y - mu) * inv * g.y + be.y;
    float o2 = (v.z - mu) * inv * g.z + be.z;
    float o3 = (v.w - mu) * inv * g.w + be.w;
    const size_t base = (size_t)row * D_ + tid * 4;
    *(float4*)(g_xn + base) = make_float4(o0, o1, o2, o3);
    __nv_bfloat16 h0 = __float2bfloat16(o0), h1 = __float2bfloat16(o1);
    __nv_bfloat16 h2 = __float2bfloat16(o2), h3 = __float2bfloat16(o3);
    __nv_bfloat162 ph0, ph1, pl0, pl1;
    ph0.x = h0; ph0.y = h1; ph1.x = h2; ph1.y = h3;
    pl0.x = __float2bfloat16(o0 - __bfloat162float(h0));
    pl0.y = __float2bfloat16(o1 - __bfloat162float(h1));
    pl1.x = __float2bfloat16(o2 - __bfloat162float(h2));
    pl1.y = __float2bfloat16(o3 - __bfloat162float(h3));
    *(__nv_bfloat162*)(g_xn_hi + base)     = ph0;
    *(__nv_bfloat162*)(g_xn_hi + base + 2) = ph1;
    *(__nv_bfloat162*)(g_xn_lo + base)     = pl0;
    *(__nv_bfloat162*)(g_xn_lo + base + 2) = pl1;
}

// ---------------- rope tables: both layouts ------------------------------------
__global__ void rope_table_kernel() {
    const int idx = blockIdx.x * blockDim.x + threadIdx.x;
    if (idx >= T_ * HALF_D) return;
    const int t = idx >> 9;
    const int i = idx & (HALF_D - 1);
    const float e   = -(((float)i - 1.0f) * (1.0f / 512.0f));
    const float inv = expf(e * 11.512925464970229f);   // ln(1e5)
    float sn, cs;
    sincosf((float)t * inv, &sn, &cs);
    g_sin [idx] = sn;
    g_cos [idx] = cs;
    g_sinT[i * T_ + t] = sn;
    g_cosT[i * T_ + t] = cs;
}

// ---------------- sequence lengths ---------------------------------------------
__global__ void len_kernel(const unsigned int* __restrict__ mask) {
    __shared__ int sc[8];
    const int b = blockIdx.x, tid = threadIdx.x;
    int c = 0;
    for (int i = tid; i < T_; i += 256) c += (mask[b * T_ + i] != 0u);
    #pragma unroll
    for (int o = 16; o > 0; o >>= 1) c += __shfl_down_sync(0xffffffffu, c, o);
    if ((tid & 31) == 0) sc[tid >> 5] = c;
    __syncthreads();
    if (tid == 0) {
        int t = 0;
        #pragma unroll
        for (int i = 0; i < 8; i++) t += sc[i];
        g_len[b] = t;
    }
}

// ---------------- weight transpose + bf16 split:  W[k][n] -> Wt[n][k] ----------
__global__ void wsplit_kernel(const float* __restrict__ W,
                              __nv_bfloat16* __restrict__ Whi,
                              __nv_bfloat16* __restrict__ Wlo, int N) {
    __shared__ float tile[32][33];
    const int tx = threadIdx.x, ty = threadIdx.y;
    const int n0 = blockIdx.x * 32, k0 = blockIdx.y * 32;
    #pragma unroll
    for (int j = 0; j < 32; j += 8)
        tile[ty + j][tx] = W[(size_t)(k0 + ty + j) * N + n0 + tx];
    __syncthreads();
    #pragma unroll
    for (int j = 0; j < 32; j += 8) {
        float v = tile[tx][ty + j];
        const int n = n0 + ty + j, k = k0 + tx;
        __nv_bfloat16 h = __float2bfloat16(v);
        Whi[(size_t)n * 1024 + k] = h;
        Wlo[(size_t)n * 1024 + k] = __float2bfloat16(v - __bfloat162float(h));
    }
}

// ---------------- WMMA bf16-split GEMM (official API, no inline asm) -----------
// CTA 128x128, 8 warps (4m x 2n), warp tile 32x64, wmma 16x16x16.
// K-chunk 16; rows padded to 24 bf16 (48 B); static smem 48 KB, reused as
// a per-warp f32 epilogue buffer after the mainloop.
enum { RSTR = 48, LDMS = 24, PART_SZ = 128 * RSTR,          // 6144
       P_AH = 0, P_AL = PART_SZ, P_BH = 2*PART_SZ, P_BL = 3*PART_SZ,
       STAGE = 4*PART_SZ };                                 // 24576

template<int NTOT, bool ROPE>
__global__ void __launch_bounds__(256, 2) gemm_wmma(
    const __nv_bfloat16* __restrict__ Ahi, const __nv_bfloat16* __restrict__ Alo,
    const __nv_bfloat16* __restrict__ Bhi, const __nv_bfloat16* __restrict__ Blo,
    const float* __restrict__ bias, float* __restrict__ C)
{
    __shared__ __align__(16) char smem[2 * STAGE];          // 49152 static
    const int tid = threadIdx.x;
    const int lane = tid & 31, wid = tid >> 5;
    const int wm = wid >> 1, wn = wid & 1;
    const int bm = blockIdx.y, bn = blockIdx.x;

    // staging: row = tid>>1 (0..127), half = tid&1, 16 B each (32 B/row/chunk)
    const int sr = tid >> 1, sh = tid & 1;
    const uint32_t soff = sr * RSTR + sh * 16;
    const char* gAH = (const char*)Ahi + (size_t)(bm*128 + sr) * 2048 + sh * 16;
    const char* gAL = (const char*)Alo + (size_t)(bm*128 + sr) * 2048 + sh * 16;
    const char* gBH = (const char*)Bhi + (size_t)(bn*128 + sr) * 2048 + sh * 16;
    const char* gBL = (const char*)Blo + (size_t)(bn*128 + sr) * 2048 + sh * 16;

    wmma::fragment<wmma::accumulator, 16, 16, 16, float> acc[2][4];
    #pragma unroll
    for (int mi = 0; mi < 2; mi++)
        #pragma unroll
        for (int nj = 0; nj < 4; nj++)
            wmma::fill_fragment(acc[mi][nj], 0.0f);

    // preload chunk 0, stage into buffer 0
    float4 rAH = *(const float4*)(gAH);
    float4 rAL = *(const float4*)(gAL);
    float4 rBH = *(const float4*)(gBH);
    float4 rBL = *(const float4*)(gBL);
    *(float4*)(smem + P_AH + soff) = rAH;
    *(float4*)(smem + P_AL + soff) = rAL;
    *(float4*)(smem + P_BH + soff) = rBH;
    *(float4*)(smem + P_BL + soff) = rBL;
    __syncthreads();

    for (int c = 0; c < 64; c++) {
        const int buf = c & 1;
        if (c < 63) {
            const int off = (c + 1) * 32;
            rAH = *(const float4*)(gAH + off);
            rAL = *(const float4*)(gAL + off);
            rBH = *(const float4*)(gBH + off);
            rBL = *(const float4*)(gBL + off);
        }

        const __nv_bfloat16* sAh = (const __nv_bfloat16*)(smem + buf*STAGE + P_AH);
        const __nv_bfloat16* sAl = (const __nv_bfloat16*)(smem + buf*STAGE + P_AL);
        const __nv_bfloat16* sBh = (const __nv_bfloat16*)(smem + buf*STAGE + P_BH);
        const __nv_bfloat16* sBl = (const __nv_bfloat16*)(smem + buf*STAGE + P_BL);

        wmma::fragment<wmma::matrix_b, 16, 16, 16, __nv_bfloat16, wmma::col_major> fbh[4], fbl[4];
        #pragma unroll
        for (int nj = 0; nj < 4; nj++) {
            wmma::load_matrix_sync(fbh[nj], sBh + (wn*64 + nj*16) * LDMS, LDMS);
            wmma::load_matrix_sync(fbl[nj], sBl + (wn*64 + nj*16) * LDMS, LDMS);
        }
        #pragma unroll
        for (int mi = 0; mi < 2; mi++) {
            wmma::fragment<wmma::matrix_a, 16, 16, 16, __nv_bfloat16, wmma::row_major> fah, fal;
            wmma::load_matrix_sync(fah, sAh + (wm*32 + mi*16) * LDMS, LDMS);
            wmma::load_matrix_sync(fal, sAl + (wm*32 + mi*16) * LDMS, LDMS);
            #pragma unroll
            for (int nj = 0; nj < 4; nj++) {
                wmma::mma_sync(acc[mi][nj], fah, fbh[nj], acc[mi][nj]);
                wmma::mma_sync(acc[mi][nj], fah, fbl[nj], acc[mi][nj]);
                wmma::mma_sync(acc[mi][nj], fal, fbh[nj], acc[mi][nj]);
            }
        }
        __syncthreads();
        if (c < 63) {
            char* sN = smem + (buf ^ 1) * STAGE;
            *(float4*)(sN + P_AH + soff) = rAH;
            *(float4*)(sN + P_AL + soff) = rAL;
            *(float4*)(sN + P_BH + soff) = rBH;
            *(float4*)(sN + P_BL + soff) = rBL;
            __syncthreads();
        }
    }

    // epilogue: per-warp smem buffer (16x64 f32 = 4 KB per warp; staging dead)
    float* sepi = (float*)(smem) + wid * 1024;
    const int r    = lane >> 1;           // 0..15
    const int cseg = (lane & 1) * 32;     // 0 or 32
    #pragma unroll 1
    for (int mi = 0; mi < 2; mi++) {
        #pragma unroll
        for (int nj = 0; nj < 4; nj++)
            wmma::store_matrix_sync(sepi + nj*16, acc[mi][nj], 64, wmma::mem_row_major);
        __syncwarp();
        const int row = bm*128 + wm*32 + mi*16 + r;
        const int t   = row & (T_ - 1);
        #pragma unroll
        for (int p = 0; p < 16; p++) {
            const int cl  = cseg + 2*p;
            const int col = bn*128 + wn*64 + cl;
            float e = sepi[r*64 + cl]     + __ldg(bias + col);
            float o = sepi[r*64 + cl + 1] + __ldg(bias + col + 1);
            float2 v;
            if (ROPE) {
                const int pi = (col & (D_ - 1)) >> 1;
                const float sn = g_sinT[pi * T_ + t];
                const float cs = g_cosT[pi * T_ + t];
                v.x = fmaf(e, cs, -o * sn);
                v.y = fmaf(o, cs,  e * sn);
            } else {
                v.x = e; v.y = o;
            }
            *(float2*)(C + (size_t)row * NTOT + col) = v;
        }
        __syncwarp();
    }
}

// ---------------- check kernels: verify MMA output, set fallback flag ----------
__global__ void __launch_bounds__(256) check_qkv_kernel(
    const float* __restrict__ W, const float* __restrict__ bias) {
    __shared__ int bad;
    const int tid = threadIdx.x, lane = tid & 31, w = tid >> 5;
    if (tid == 0) bad = 0;
    __syncthreads();
    const int row = (w * 1237 + 11) & (M_ - 1);
    const int c0  = ((w * 677) % (N3_ / 64)) * 64;
    const int ce  = c0 + lane * 2;
    const float* xr = g_xn + (size_t)row * D_;
    float se = 0.f, so = 0.f;
    for (int k = 0; k < D_; k++) {
        const float xv = xr[k];
        se = fmaf(xv, W[(size_t)k * N3_ + ce],     se);
        so = fmaf(xv, W[(size_t)k * N3_ + ce + 1], so);
    }
    se += bias[ce]; so += bias[ce + 1];
    const int t  = row & (T_ - 1);
    const int pi = (ce & (D_ - 1)) >> 1;
    const float sn = g_sinT[pi * T_ + t], cs = g_cosT[pi * T_ + t];
    const float re = se * cs - so * sn;
    const float ro = so * cs + se * sn;
    const float ge = g_qkv[(size_t)row * N3_ + ce];
    const float go = g_qkv[(size_t)row * N3_ + ce + 1];
    if (fabsf(ge - re) > 0.01f + 0.003f * fabsf(re) ||
        fabsf(go - ro) > 0.01f + 0.003f * fabsf(ro)) bad = 1;
    __syncthreads();
    if (tid == 0) g_flag_q = bad;
}

__global__ void __launch_bounds__(256) check_out_kernel(
    const float* __restrict__ W, const float* __restrict__ bias,
    const float* __restrict__ out) {
    __shared__ int bad;
    const int tid = threadIdx.x, lane = tid & 31, w = tid >> 5;
    if (tid == 0) bad = 0;
    __syncthreads();
    const int row = (w * 1237 + 17) & (M_ - 1);
    const int c0  = ((w * 677) % (D_ / 64)) * 64;
    const int ce  = c0 + lane * 2;
    const float* ar = g_attn + (size_t)row * D_;
    float se = 0.f, so = 0.f;
    for (int k = 0; k < D_; k++) {
        const float av = ar[k];
        se = fmaf(av, W[(size_t)k * D_ + ce],     se);
        so = fmaf(av, W[(size_t)k * D_ + ce + 1], so);
    }
    se += bias[ce]; so += bias[ce + 1];
    const float ge = out[(size_t)row * D_ + ce];
    const float go = out[(size_t)row * D_ + ce + 1];
    if (fabsf(ge - se) > 0.01f + 0.003f * fabsf(se) ||
        fabsf(go - so) > 0.01f + 0.003f * fabsf(so)) bad = 1;
    __syncthreads();
    if (tid == 0) g_flag_o = bad;
}

// ---------------- fp32 SGEMM fallback (round-1 proven), flag-gated -------------
template<int N, bool ROPE>
__device__ __forceinline__ void gemm_body(const float* __restrict__ A,
                                          const float* __restrict__ Bm,
                                          const float* __restrict__ bias,
                                          float* __restrict__ C) {
    __shared__ float As[8][128];
    __shared__ float Bs[8][128];
    const int tid = threadIdx.x;
    const int bm = blockIdx.y, bn = blockIdx.x;
    const int arow = tid >> 1, acol = (tid & 1) << 2;
    const int brow = tid >> 5, bcol = (tid & 31) << 2;
    const int tx = tid & 15, ty = tid >> 4;

    const float* Ap = A + (size_t)(bm * 128 + arow) * 1024 + acol;
    const float* Bp = Bm + (size_t)brow * N + bn * 128 + bcol;

    float acc[8][8];
    #pragma unroll
    for (int i = 0; i < 8; i++)
        #pragma unroll
        for (int j = 0; j < 8; j++) acc[i][j] = 0.f;

    for (int k0 = 0; k0 < 1024; k0 += 8) {
        float4 a4 = *(const float4*)(Ap + k0);
        float4 b4 = *(const float4*)(Bp + (size_t)k0 * N);
        As[acol + 0][arow] = a4.x;
        As[acol + 1][arow] = a4.y;
        As[acol + 2][arow] = a4.z;
        As[acol + 3][arow] = a4.w;
        *(float4*)(&Bs[brow][bcol]) = b4;
        __syncthreads();
        #pragma unroll
        for (int kk = 0; kk < 8; kk++) {
            float4 a0 = *(const float4*)(&As[kk][ty * 8]);
            float4 a1 = *(const float4*)(&As[kk][ty * 8 + 4]);
            float4 b0 = *(const float4*)(&Bs[kk][tx * 8]);
            float4 b1 = *(const float4*)(&Bs[kk][tx * 8 + 4]);
            float ar[8] = {a0.x, a0.y, a0.z, a0.w, a1.x, a1.y, a1.z, a1.w};
            float br[8] = {b0.x, b0.y, b0.z, b0.w, b1.x, b1.y, b1.z, b1.w};
            #pragma unroll
            for (int i = 0; i < 8; i++)
                #pragma unroll
                for (int j = 0; j < 8; j++)
                    acc[i][j] = fmaf(ar[i], br[j], acc[i][j]);
        }
        __syncthreads();
    }

    const int row0 = bm * 128 + ty * 8;
    const int col0 = bn * 128 + tx * 8;
    #pragma unroll
    for (int i = 0; i < 8; i++) {
        const int r = row0 + i;
        if (ROPE) {
            const int t = r & (T_ - 1);
            #pragma unroll
            for (int j = 0; j < 8; j += 2) {
                const int c  = col0 + j;
                const int pi = (c & (D_ - 1)) >> 1;
                const float sn = g_sin[t * HALF_D + pi];
                const float cs = g_cos[t * HALF_D + pi];
                const float e = acc[i][j]     + bias[c];
                const float o = acc[i][j + 1] + bias[c + 1];
                acc[i][j]     = fmaf(e, cs, -o * sn);
                acc[i][j + 1] = fmaf(o, cs,  e * sn);
            }
        } else {
            #pragma unroll
            for (int j = 0; j < 8; j++) acc[i][j] += bias[col0 + j];
        }
        float4* out = (float4*)(C + (size_t)r * N + col0);
        out[0] = make_float4(acc[i][0], acc[i][1], acc[i][2], acc[i][3]);
        out[1] = make_float4(acc[i][4], acc[i][5], acc[i][6], acc[i][7]);
    }
}

__global__ void __launch_bounds__(256) gemm_fb_qkv(const float* __restrict__ Wqkv,
                                                   const float* __restrict__ bqkv) {
    if (g_flag_q == 0) return;
    gemm_body<N3_, true>(g_xn, Wqkv, bqkv, g_qkv);
}

__global__ void __launch_bounds__(256) gemm_fb_out(const float* __restrict__ Wout,
                                                   const float* __restrict__ bout,
                                                   float* __restrict__ out) {
    if (g_flag_o == 0) return;
    gemm_body<D_, false>(g_attn, Wout, bout, out);
}

// ---------------- flash attention (fp32), emits fp32 + bf16 hi/lo --------------
__global__ void __launch_bounds__(256, 1) attn_kernel() {
    __shared__ float ks[32][64];
    __shared__ float vs[32][64];
    __shared__ float scr[32][256];

    const int bh = blockIdx.y;
    const int b = bh >> 4, h = bh & 15;
    const int tid = threadIdx.x;
    const int t = blockIdx.x * 256 + tid;
    const int len = g_len[b];

    const float* qrow = g_qkv + (size_t)(b * T_ + t) * N3_ + h * DH_;
    float q[64];
    #pragma unroll
    for (int i = 0; i < 16; i++) {
        float4 v4 = *(const float4*)(qrow + i * 4);
        q[i*4+0] = v4.x; q[i*4+1] = v4.y; q[i*4+2] = v4.z; q[i*4+3] = v4.w;
    }
    float o[64];
    #pragma unroll
    for (int d = 0; d < 64; d++) o[d] = 0.f;
    float m = -1e30f, l = 0.f;

    const float* kbase = g_qkv + (size_t)(b * T_) * N3_ + D_     + h * DH_;
    const float* vbase = g_qkv + (size_t)(b * T_) * N3_ + 2 * D_ + h * DH_;

    for (int s0 = 0; s0 < T_; s0 += 32) {
        if (s0 >= len) break;
        #pragma unroll
        for (int p = 0; p < 2; p++) {
            const int idx = tid * 2 + p;
            const int r = idx >> 4, c = (idx & 15) << 2;
            *(float4*)&ks[r][c] = *(const float4*)(kbase + (size_t)(s0 + r) * N3_ + c);
            *(float4*)&vs[r][c] = *(const float4*)(vbase + (size_t)(s0 + r) * N3_ + c);
        }
        __syncthreads();

        const int nv = min(32, len - s0);
        float tmax = -1e30f;
        for (int s = 0; s < 32; s++) {
            float acc = 0.f;
            #pragma unroll
            for (int d4 = 0; d4 < 16; d4++) {
                float4 kv = *(const float4*)&ks[s][d4 * 4];
                acc = fmaf(q[d4*4+0], kv.x, acc);
                acc = fmaf(q[d4*4+1], kv.y, acc);
                acc = fmaf(q[d4*4+2], kv.z, acc);
                acc = fmaf(q[d4*4+3], kv.w, acc);
            }
            acc *= 0.125f;
            scr[s][tid] = acc;
            if (s < nv) tmax = fmaxf(tmax, acc);
        }
        const float mnew = fmaxf(m, tmax);
        const float corr = expf(m - mnew);
        l *= corr;
        #pragma unroll
        for (int d = 0; d < 64; d++) o[d] *= corr;
        for (int s = 0; s < nv; s++) {
            const float p = expf(scr[s][tid] - mnew);
            l += p;
            #pragma unroll
            for (int d4 = 0; d4 < 16; d4++) {
                float4 vv = *(const float4*)&vs[s][d4 * 4];
                o[d4*4+0] = fmaf(p, vv.x, o[d4*4+0]);
                o[d4*4+1] = fmaf(p, vv.y, o[d4*4+1]);
                o[d4*4+2] = fmaf(p, vv.z, o[d4*4+2]);
                o[d4*4+3] = fmaf(p, vv.w, o[d4*4+3]);
            }
        }
        m = mnew;
        __syncthreads();
    }

    const float invl = 1.f / l;
    const size_t obase = (size_t)(b * T_ + t) * D_ + h * DH_;
    float* of = g_attn + obase;
    __nv_bfloat162* oh = (__nv_bfloat162*)(g_at_hi + obase);
    __nv_bfloat162* ol = (__nv_bfloat162*)(g_at_lo + obase);
    #pragma unroll
    for (int i = 0; i < 32; i++) {
        const float a = o[2*i] * invl, c2 = o[2*i+1] * invl;
        *(float2*)(of + 2*i) = make_float2(a, c2);
        __nv_bfloat16 ah = __float2bfloat16(a), ch = __float2bfloat16(c2);
        __nv_bfloat162 ph, pl;
        ph.x = ah; ph.y = ch;
        pl.x = __float2bfloat16(a  - __bfloat162float(ah));
        pl.y = __float2bfloat16(c2 - __bfloat162float(ch));
        oh[i] = ph;
        ol[i] = pl;
    }
}

// ---------------- launch -------------------------------------------------------
extern "C" void kernel_launch(void* const* d_in, const int* in_sizes, int n_in,
                              void* d_out, int out_size) {
    const float*        x     = (const float*)d_in[0];
    const unsigned int* mask  = (const unsigned int*)d_in[1];
    const float*        gamma = (const float*)d_in[2];
    const float*        beta  = (const float*)d_in[3];
    const float*        Wqkv  = (const float*)d_in[4];
    const float*        bqkv  = (const float*)d_in[5];
    const float*        Wout  = (const float*)d_in[6];
    const float*        bout  = (const float*)d_in[7];
    float* out = (float*)d_out;

    ln_kernel<<<M_, 256>>>(x, gamma, beta);
    rope_table_kernel<<<(T_ * HALF_D + 255) / 256, 256>>>();
    len_kernel<<<B_, 256>>>(mask);
    wsplit_kernel<<<dim3(N3_/32, D_/32), dim3(32, 8)>>>(Wqkv, g_wq_hi, g_wq_lo, N3_);
    wsplit_kernel<<<dim3(D_/32,  D_/32), dim3(32, 8)>>>(Wout, g_wo_hi, g_wo_lo, D_);

    // QKV: wmma attempt -> verify -> flag-gated fp32 fallback
    gemm_wmma<N3_, true><<<dim3(N3_/128, M_/128), 256>>>(
        g_xn_hi, g_xn_lo, g_wq_hi, g_wq_lo, bqkv, g_qkv);
    check_qkv_kernel<<<1, 256>>>(Wqkv, bqkv);
    gemm_fb_qkv<<<dim3(N3_/128, M_/128), 256>>>(Wqkv, bqkv);

    attn_kernel<<<dim3(T_/256, B_*H_), 256>>>();

    // Out-proj: wmma attempt -> verify -> flag-gated fp32 fallback
    gemm_wmma<D_, false><<<dim3(D_/128, M_/128), 256>>>(
        g_at_hi, g_at_lo, g_wo_hi, g_wo_lo, bout, out);
    check_out_kernel<<<1, 256>>>(Wout, bout, out);
    gemm_fb_out<<<dim3(D_/128, M_/128), 256>>>(Wout, bout, out);
}

// round 8
// speedup vs baseline: 2.4728x; 2.4728x over previous
#include <cuda_runtime.h>
#include <math.h>
#include <cstdint>

#define B_  8
#define T_  1024
#define D_  1024
#define H_  16
#define DH_ 64
#define M_  (B_*T_)     // 8192
#define N3_ (3*D_)      // 3072
#define HALF_D 512

typedef unsigned long long ull;

// ---------------- packed f32x2 ops (PTX ISA 8.6, sm_100+) ---------------------
#define FMA2(d, a, b, c) \
    asm("fma.rn.f32x2 %0, %1, %2, %3;" : "=l"(d) : "l"(a), "l"(b), "l"(c))
#define MUL2(d, a, b) \
    asm("mul.rn.f32x2 %0, %1, %2;" : "=l"(d) : "l"(a), "l"(b))
#define PACK2(d, x) \
    asm("mov.b64 %0, {%1, %1};" : "=l"(d) : "r"(__float_as_uint(x)))
#define UNPACK2(lo, hi, in) \
    asm("mov.b64 {%0, %1}, %2;" : "=f"(lo), "=f"(hi) : "l"(in))

// ---------------- scratch -------------------------------------------------------
__device__ __align__(1024) float g_xn[(size_t)M_*D_];
__device__ __align__(1024) float g_qkv[(size_t)M_*N3_];
__device__ __align__(1024) float g_attn[(size_t)M_*D_];
__device__ float g_sin[T_*HALF_D];      // [t][pair]
__device__ float g_cos[T_*HALF_D];
__device__ int   g_len[B_];
__device__ int   g_flag_q, g_flag_a, g_flag_o;

// ---------------- layernorm -----------------------------------------------------
__global__ void __launch_bounds__(256) ln_kernel(const float* __restrict__ x,
                                                 const float* __restrict__ gamma,
                                                 const float* __restrict__ beta) {
    __shared__ float ssum[8], ssq[8];
    const int row = blockIdx.x;
    const int tid = threadIdx.x;
    float4 v = *(const float4*)(x + (size_t)row * D_ + tid * 4);
    float s = v.x + v.y + v.z + v.w;
    float q = v.x*v.x + v.y*v.y + v.z*v.z + v.w*v.w;
    #pragma unroll
    for (int o = 16; o > 0; o >>= 1) {
        s += __shfl_down_sync(0xffffffffu, s, o);
        q += __shfl_down_sync(0xffffffffu, q, o);
    }
    if ((tid & 31) == 0) { ssum[tid >> 5] = s; ssq[tid >> 5] = q; }
    __syncthreads();
    float ts = 0.f, tq = 0.f;
    #pragma unroll
    for (int i = 0; i < 8; i++) { ts += ssum[i]; tq += ssq[i]; }
    const float mu  = ts * (1.f / 1024.f);
    const float var = tq * (1.f / 1024.f) - mu * mu;
    const float inv = rsqrtf(var + 1e-5f);
    float4 g  = *(const float4*)(gamma + tid * 4);
    float4 be = *(const float4*)(beta  + tid * 4);
    float4 out;
    out.x = (v.x - mu) * inv * g.x + be.x;
    out.y = (v.y - mu) * inv * g.y + be.y;
    out.z = (v.z - mu) * inv * g.z + be.z;
    out.w = (v.w - mu) * inv * g.w + be.w;
    *(float4*)(g_xn + (size_t)row * D_ + tid * 4) = out;
}

// ---------------- rope tables ----------------------------------------------------
__global__ void rope_table_kernel() {
    const int idx = blockIdx.x * blockDim.x + threadIdx.x;
    if (idx >= T_ * HALF_D) return;
    const int t = idx >> 9;
    const int i = idx & (HALF_D - 1);
    const float e   = -(((float)i - 1.0f) * (1.0f / 512.0f));
    const float inv = expf(e * 11.512925464970229f);   // ln(1e5)
    float sn, cs;
    sincosf((float)t * inv, &sn, &cs);
    g_sin[idx] = sn;
    g_cos[idx] = cs;
}

// ---------------- sequence lengths ------------------------------------------------
__global__ void len_kernel(const unsigned int* __restrict__ mask) {
    __shared__ int sc[8];
    const int b = blockIdx.x, tid = threadIdx.x;
    int c = 0;
    for (int i = tid; i < T_; i += 256) c += (mask[b * T_ + i] != 0u);
    #pragma unroll
    for (int o = 16; o > 0; o >>= 1) c += __shfl_down_sync(0xffffffffu, c, o);
    if ((tid & 31) == 0) sc[tid >> 5] = c;
    __syncthreads();
    if (tid == 0) {
        int t = 0;
        #pragma unroll
        for (int i = 0; i < 8; i++) t += sc[i];
        g_len[b] = t;
    }
}

// ---------------- f32x2 SGEMM: 128x128 tile, 8x8/thread (packed pairs) ------------
template<int N, bool ROPE>
__global__ void __launch_bounds__(256) gemm_x2(const float* __restrict__ A,
                                               const float* __restrict__ Bm,
                                               const float* __restrict__ bias,
                                               float* __restrict__ C) {
    __shared__ float As[8][128];
    __shared__ float Bs[8][128];
    const int tid = threadIdx.x;
    const int bm = blockIdx.y, bn = blockIdx.x;
    const int arow = tid >> 1, acol = (tid & 1) << 2;
    const int brow = tid >> 5, bcol = (tid & 31) << 2;
    const int tx = tid & 15, ty = tid >> 4;

    const float* Ap = A + (size_t)(bm * 128 + arow) * 1024 + acol;
    const float* Bp = Bm + (size_t)brow * N + bn * 128 + bcol;

    ull acc2[8][4];
    #pragma unroll
    for (int i = 0; i < 8; i++)
        #pragma unroll
        for (int j = 0; j < 4; j++) acc2[i][j] = 0ull;

    float4 a4 = *(const float4*)(Ap);
    float4 b4 = *(const float4*)(Bp);

    for (int k0 = 0; k0 < 1024; k0 += 8) {
        As[acol + 0][arow] = a4.x;
        As[acol + 1][arow] = a4.y;
        As[acol + 2][arow] = a4.z;
        As[acol + 3][arow] = a4.w;
        *(float4*)(&Bs[brow][bcol]) = b4;
        __syncthreads();
        if (k0 + 8 < 1024) {                 // prefetch next slice into regs
            a4 = *(const float4*)(Ap + k0 + 8);
            b4 = *(const float4*)(Bp + (size_t)(k0 + 8) * N);
        }
        #pragma unroll
        for (int kk = 0; kk < 8; kk++) {
            float4 a0 = *(const float4*)(&As[kk][ty * 8]);
            float4 a1 = *(const float4*)(&As[kk][ty * 8 + 4]);
            ulonglong2 bp0 = *(const ulonglong2*)(&Bs[kk][tx * 8]);
            ulonglong2 bp1 = *(const ulonglong2*)(&Bs[kk][tx * 8 + 4]);
            ull b2[4] = {bp0.x, bp0.y, bp1.x, bp1.y};
            float ar[8] = {a0.x, a0.y, a0.z, a0.w, a1.x, a1.y, a1.z, a1.w};
            #pragma unroll
            for (int i = 0; i < 8; i++) {
                ull a2; PACK2(a2, ar[i]);
                FMA2(acc2[i][0], a2, b2[0], acc2[i][0]);
                FMA2(acc2[i][1], a2, b2[1], acc2[i][1]);
                FMA2(acc2[i][2], a2, b2[2], acc2[i][2]);
                FMA2(acc2[i][3], a2, b2[3], acc2[i][3]);
            }
        }
        __syncthreads();
    }

    const int row0 = bm * 128 + ty * 8;
    const int col0 = bn * 128 + tx * 8;
    #pragma unroll
    for (int i = 0; i < 8; i++) {
        const int r = row0 + i;
        const int t = r & (T_ - 1);
        float vals[8];
        #pragma unroll
        for (int j = 0; j < 4; j++) {
            float e, o;
            UNPACK2(e, o, acc2[i][j]);
            const int c = col0 + 2 * j;
            e += bias[c];
            o += bias[c + 1];
            if (ROPE) {
                const int pi = (c & (D_ - 1)) >> 1;
                const float sn = g_sin[t * HALF_D + pi];
                const float cs = g_cos[t * HALF_D + pi];
                vals[2*j]     = fmaf(e, cs, -o * sn);
                vals[2*j + 1] = fmaf(o, cs,  e * sn);
            } else {
                vals[2*j] = e; vals[2*j + 1] = o;
            }
        }
        float4* out = (float4*)(C + (size_t)r * N + col0);
        out[0] = make_float4(vals[0], vals[1], vals[2], vals[3]);
        out[1] = make_float4(vals[4], vals[5], vals[6], vals[7]);
    }
}

// ---------------- fp32 SGEMM fallback (round-1 proven) ---------------------------
template<int N, bool ROPE>
__device__ __forceinline__ void gemm_body(const float* __restrict__ A,
                                          const float* __restrict__ Bm,
                                          const float* __restrict__ bias,
                                          float* __restrict__ C) {
    __shared__ float As[8][128];
    __shared__ float Bs[8][128];
    const int tid = threadIdx.x;
    const int bm = blockIdx.y, bn = blockIdx.x;
    const int arow = tid >> 1, acol = (tid & 1) << 2;
    const int brow = tid >> 5, bcol = (tid & 31) << 2;
    const int tx = tid & 15, ty = tid >> 4;

    const float* Ap = A + (size_t)(bm * 128 + arow) * 1024 + acol;
    const float* Bp = Bm + (size_t)brow * N + bn * 128 + bcol;

    float acc[8][8];
    #pragma unroll
    for (int i = 0; i < 8; i++)
        #pragma unroll
        for (int j = 0; j < 8; j++) acc[i][j] = 0.f;

    for (int k0 = 0; k0 < 1024; k0 += 8) {
        float4 a4 = *(const float4*)(Ap + k0);
        float4 b4 = *(const float4*)(Bp + (size_t)k0 * N);
        As[acol + 0][arow] = a4.x;
        As[acol + 1][arow] = a4.y;
        As[acol + 2][arow] = a4.z;
        As[acol + 3][arow] = a4.w;
        *(float4*)(&Bs[brow][bcol]) = b4;
        __syncthreads();
        #pragma unroll
        for (int kk = 0; kk < 8; kk++) {
            float4 a0 = *(const float4*)(&As[kk][ty * 8]);
            float4 a1 = *(const float4*)(&As[kk][ty * 8 + 4]);
            float4 b0 = *(const float4*)(&Bs[kk][tx * 8]);
            float4 b1 = *(const float4*)(&Bs[kk][tx * 8 + 4]);
            float ar[8] = {a0.x, a0.y, a0.z, a0.w, a1.x, a1.y, a1.z, a1.w};
            float br[8] = {b0.x, b0.y, b0.z, b0.w, b1.x, b1.y, b1.z, b1.w};
            #pragma unroll
            for (int i = 0; i < 8; i++)
                #pragma unroll
                for (int j = 0; j < 8; j++)
                    acc[i][j] = fmaf(ar[i], br[j], acc[i][j]);
        }
        __syncthreads();
    }

    const int row0 = bm * 128 + ty * 8;
    const int col0 = bn * 128 + tx * 8;
    #pragma unroll
    for (int i = 0; i < 8; i++) {
        const int r = row0 + i;
        if (ROPE) {
            const int t = r & (T_ - 1);
            #pragma unroll
            for (int j = 0; j < 8; j += 2) {
                const int c  = col0 + j;
                const int pi = (c & (D_ - 1)) >> 1;
                const float sn = g_sin[t * HALF_D + pi];
                const float cs = g_cos[t * HALF_D + pi];
                const float e = acc[i][j]     + bias[c];
                const float o = acc[i][j + 1] + bias[c + 1];
                acc[i][j]     = fmaf(e, cs, -o * sn);
                acc[i][j + 1] = fmaf(o, cs,  e * sn);
            }
        } else {
            #pragma unroll
            for (int j = 0; j < 8; j++) acc[i][j] += bias[col0 + j];
        }
        float4* out = (float4*)(C + (size_t)r * N + col0);
        out[0] = make_float4(acc[i][0], acc[i][1], acc[i][2], acc[i][3]);
        out[1] = make_float4(acc[i][4], acc[i][5], acc[i][6], acc[i][7]);
    }
}

__global__ void __launch_bounds__(256) gemm_fb_qkv(const float* __restrict__ W,
                                                   const float* __restrict__ b) {
    if (g_flag_q == 0) return;
    gemm_body<N3_, true>(g_xn, W, b, g_qkv);
}
__global__ void __launch_bounds__(256) gemm_fb_out(const float* __restrict__ W,
                                                   const float* __restrict__ b,
                                                   float* __restrict__ out) {
    if (g_flag_o == 0) return;
    gemm_body<D_, false>(g_attn, W, b, out);
}

// ---------------- check kernels --------------------------------------------------
__global__ void __launch_bounds__(256) check_qkv_kernel(
    const float* __restrict__ W, const float* __restrict__ bias) {
    __shared__ int bad;
    const int tid = threadIdx.x, lane = tid & 31, w = tid >> 5;
    if (tid == 0) bad = 0;
    __syncthreads();
    const int row = (w * 1237 + 11) & (M_ - 1);
    const int c0  = ((w * 677) % (N3_ / 64)) * 64;
    const int ce  = c0 + lane * 2;
    const float* xr = g_xn + (size_t)row * D_;
    float se = 0.f, so = 0.f;
    for (int k = 0; k < D_; k++) {
        const float xv = xr[k];
        se = fmaf(xv, W[(size_t)k * N3_ + ce],     se);
        so = fmaf(xv, W[(size_t)k * N3_ + ce + 1], so);
    }
    se += bias[ce]; so += bias[ce + 1];
    const int t  = row & (T_ - 1);
    const int pi = (ce & (D_ - 1)) >> 1;
    const float sn = g_sin[t * HALF_D + pi], cs = g_cos[t * HALF_D + pi];
    const float re = se * cs - so * sn;
    const float ro = so * cs + se * sn;
    const float ge = g_qkv[(size_t)row * N3_ + ce];
    const float go = g_qkv[(size_t)row * N3_ + ce + 1];
    if (fabsf(ge - re) > 0.01f + 0.003f * fabsf(re) ||
        fabsf(go - ro) > 0.01f + 0.003f * fabsf(ro)) bad = 1;
    __syncthreads();
    if (tid == 0) g_flag_q = bad;
}

__global__ void __launch_bounds__(256) check_attn_kernel() {
    __shared__ int bad;
    const int tid = threadIdx.x, lane = tid & 31, w = tid >> 5;
    if (tid == 0) bad = 0;
    __syncthreads();
    const int b = w;
    const int h = (w * 5) & 15;
    const int t = (w * 373 + 29) & (T_ - 1);
    const int len = g_len[b];
    const float* qrow = g_qkv + (size_t)(b*T_ + t)*N3_ + h*DH_;
    float q[64];
    for (int i = 0; i < 64; i++) q[i] = qrow[i];
    float arr[32];
    const int nj = (len + 31) >> 5;
    float mmax = -1e30f;
    for (int j = 0; j < nj; j++) {
        const int s = lane + 32*j;
        float sc = -1e30f;
        if (s < len) {
            const float* kr = g_qkv + (size_t)(b*T_ + s)*N3_ + D_ + h*DH_;
            float acc = 0.f;
            for (int d = 0; d < 64; d++) acc = fmaf(q[d], kr[d], acc);
            sc = acc * 0.125f;
            mmax = fmaxf(mmax, sc);
        }
        arr[j] = sc;
    }
    #pragma unroll
    for (int o = 16; o > 0; o >>= 1)
        mmax = fmaxf(mmax, __shfl_xor_sync(0xffffffffu, mmax, o));
    float l = 0.f;
    for (int j = 0; j < nj; j++) {
        const int s = lane + 32*j;
        arr[j] = (s < len) ? expf(arr[j] - mmax) : 0.f;
        l += arr[j];
    }
    #pragma unroll
    for (int o = 16; o > 0; o >>= 1) l += __shfl_xor_sync(0xffffffffu, l, o);
    const float invl = 1.f / l;
    for (int d = 0; d < 64; d++) {
        float acc = 0.f;
        for (int j = 0; j < nj; j++) {
            const int s = lane + 32*j;
            if (s < len)
                acc = fmaf(arr[j],
                           g_qkv[(size_t)(b*T_+s)*N3_ + 2*D_ + h*DH_ + d], acc);
        }
        #pragma unroll
        for (int o = 16; o > 0; o >>= 1) acc += __shfl_xor_sync(0xffffffffu, acc, o);
        if (lane == 0) {
            const float ref = acc * invl;
            const float got = g_attn[(size_t)(b*T_+t)*D_ + h*DH_ + d];
            if (fabsf(got - ref) > 0.01f + 0.01f * fabsf(ref)) bad = 1;
        }
    }
    __syncthreads();
    if (tid == 0) g_flag_a = bad;
}

__global__ void __launch_bounds__(256) check_out_kernel(
    const float* __restrict__ W, const float* __restrict__ bias,
    const float* __restrict__ out) {
    __shared__ int bad;
    const int tid = threadIdx.x, lane = tid & 31, w = tid >> 5;
    if (tid == 0) bad = 0;
    __syncthreads();
    const int row = (w * 1237 + 17) & (M_ - 1);
    const int c0  = ((w * 677) % (D_ / 64)) * 64;
    const int ce  = c0 + lane * 2;
    const float* ar = g_attn + (size_t)row * D_;
    float se = 0.f, so = 0.f;
    for (int k = 0; k < D_; k++) {
        const float av = ar[k];
        se = fmaf(av, W[(size_t)k * D_ + ce],     se);
        so = fmaf(av, W[(size_t)k * D_ + ce + 1], so);
    }
    se += bias[ce]; so += bias[ce + 1];
    const float ge = out[(size_t)row * D_ + ce];
    const float go = out[(size_t)row * D_ + ce + 1];
    if (fabsf(ge - se) > 0.01f + 0.003f * fabsf(se) ||
        fabsf(go - so) > 0.01f + 0.003f * fabsf(so)) bad = 1;
    __syncthreads();
    if (tid == 0) g_flag_o = bad;
}

// ---------------- flash attention, f32x2 packed -----------------------------------
__global__ void __launch_bounds__(256, 1) attn_x2() {
    __shared__ float ks[32][64];
    __shared__ float vs[32][64];
    __shared__ float scr[32][256];

    const int bh = blockIdx.y;
    const int b = bh >> 4, h = bh & 15;
    const int tid = threadIdx.x;
    const int t = blockIdx.x * 256 + tid;
    const int len = g_len[b];

    const ulonglong2* qr2 = (const ulonglong2*)(g_qkv + (size_t)(b*T_ + t)*N3_ + h*DH_);
    ull q2[32];
    #pragma unroll
    for (int i = 0; i < 16; i++) {
        ulonglong2 u = qr2[i];
        q2[2*i] = u.x; q2[2*i + 1] = u.y;
    }
    ull o2[32];
    #pragma unroll
    for (int i = 0; i < 32; i++) o2[i] = 0ull;
    float m = -1e30f, l = 0.f;

    const float* kbase = g_qkv + (size_t)(b * T_) * N3_ + D_     + h * DH_;
    const float* vbase = g_qkv + (size_t)(b * T_) * N3_ + 2 * D_ + h * DH_;

    for (int s0 = 0; s0 < T_; s0 += 32) {
        if (s0 >= len) break;
        #pragma unroll
        for (int p = 0; p < 2; p++) {
            const int idx = tid * 2 + p;
            const int r = idx >> 4, c = (idx & 15) << 2;
            *(float4*)&ks[r][c] = *(const float4*)(kbase + (size_t)(s0 + r) * N3_ + c);
            *(float4*)&vs[r][c] = *(const float4*)(vbase + (size_t)(s0 + r) * N3_ + c);
        }
        __syncthreads();

        const int nv = min(32, len - s0);
        float tmax = -1e30f;
        for (int s = 0; s < 32; s++) {
            ull accA = 0ull, accB = 0ull;          // two chains to cut latency
            #pragma unroll
            for (int d4 = 0; d4 < 16; d4++) {
                ulonglong2 kk2 = *(const ulonglong2*)&ks[s][d4 * 4];
                FMA2(accA, q2[2*d4],     kk2.x, accA);
                FMA2(accB, q2[2*d4 + 1], kk2.y, accB);
            }
            float ax, ay, bx, by;
            UNPACK2(ax, ay, accA);
            UNPACK2(bx, by, accB);
            const float acc = (ax + ay + bx + by) * 0.125f;
            scr[s][tid] = acc;
            if (s < nv) tmax = fmaxf(tmax, acc);
        }
        const float mnew = fmaxf(m, tmax);
        const float corr = expf(m - mnew);
        l *= corr;
        ull corr2; PACK2(corr2, corr);
        #pragma unroll
        for (int i = 0; i < 32; i++) MUL2(o2[i], o2[i], corr2);
        for (int s = 0; s < nv; s++) {
            const float p = expf(scr[s][tid] - mnew);
            l += p;
            ull p2; PACK2(p2, p);
            #pragma unroll
            for (int d4 = 0; d4 < 16; d4++) {
                ulonglong2 vv2 = *(const ulonglong2*)&vs[s][d4 * 4];
                FMA2(o2[2*d4],     p2, vv2.x, o2[2*d4]);
                FMA2(o2[2*d4 + 1], p2, vv2.y, o2[2*d4 + 1]);
            }
        }
        m = mnew;
        __syncthreads();
    }

    const float invl = 1.f / l;
    float* of = g_attn + (size_t)(b * T_ + t) * D_ + h * DH_;
    #pragma unroll
    for (int i = 0; i < 16; i++) {
        float x0, x1, x2, x3;
        UNPACK2(x0, x1, o2[2*i]);
        UNPACK2(x2, x3, o2[2*i + 1]);
        *(float4*)(of + i * 4) = make_float4(x0*invl, x1*invl, x2*invl, x3*invl);
    }
}

// ---------------- flash attention scalar fallback (round-1 proven), flag-gated ----
__global__ void __launch_bounds__(256, 1) attn_fb() {
    if (g_flag_a == 0) return;
    __shared__ float ks[32][64];
    __shared__ float vs[32][64];
    __shared__ float scr[32][256];

    const int bh = blockIdx.y;
    const int b = bh >> 4, h = bh & 15;
    const int tid = threadIdx.x;
    const int t = blockIdx.x * 256 + tid;
    const int len = g_len[b];

    const float* qrow = g_qkv + (size_t)(b * T_ + t) * N3_ + h * DH_;
    float q[64];
    #pragma unroll
    for (int i = 0; i < 16; i++) {
        float4 v4 = *(const float4*)(qrow + i * 4);
        q[i*4+0] = v4.x; q[i*4+1] = v4.y; q[i*4+2] = v4.z; q[i*4+3] = v4.w;
    }
    float o[64];
    #pragma unroll
    for (int d = 0; d < 64; d++) o[d] = 0.f;
    float m = -1e30f, l = 0.f;

    const float* kbase = g_qkv + (size_t)(b * T_) * N3_ + D_     + h * DH_;
    const float* vbase = g_qkv + (size_t)(b * T_) * N3_ + 2 * D_ + h * DH_;

    for (int s0 = 0; s0 < T_; s0 += 32) {
        if (s0 >= len) break;
        #pragma unroll
        for (int p = 0; p < 2; p++) {
            const int idx = tid * 2 + p;
            const int r = idx >> 4, c = (idx & 15) << 2;
            *(float4*)&ks[r][c] = *(const float4*)(kbase + (size_t)(s0 + r) * N3_ + c);
            *(float4*)&vs[r][c] = *(const float4*)(vbase + (size_t)(s0 + r) * N3_ + c);
        }
        __syncthreads();

        const int nv = min(32, len - s0);
        float tmax = -1e30f;
        for (int s = 0; s < 32; s++) {
            float acc = 0.f;
            #pragma unroll
            for (int d4 = 0; d4 < 16; d4++) {
                float4 kv = *(const float4*)&ks[s][d4 * 4];
                acc = fmaf(q[d4*4+0], kv.x, acc);
                acc = fmaf(q[d4*4+1], kv.y, acc);
                acc = fmaf(q[d4*4+2], kv.z, acc);
                acc = fmaf(q[d4*4+3], kv.w, acc);
            }
            acc *= 0.125f;
            scr[s][tid] = acc;
            if (s < nv) tmax = fmaxf(tmax, acc);
        }
        const float mnew = fmaxf(m, tmax);
        const float corr = expf(m - mnew);
        l *= corr;
        #pragma unroll
        for (int d = 0; d < 64; d++) o[d] *= corr;
        for (int s = 0; s < nv; s++) {
            const float p = expf(scr[s][tid] - mnew);
            l += p;
            #pragma unroll
            for (int d4 = 0; d4 < 16; d4++) {
                float4 vv = *(const float4*)&vs[s][d4 * 4];
                o[d4*4+0] = fmaf(p, vv.x, o[d4*4+0]);
                o[d4*4+1] = fmaf(p, vv.y, o[d4*4+1]);
                o[d4*4+2] = fmaf(p, vv.z, o[d4*4+2]);
                o[d4*4+3] = fmaf(p, vv.w, o[d4*4+3]);
            }
        }
        m = mnew;
        __syncthreads();
    }

    const float invl = 1.f / l;
    float* of = g_attn + (size_t)(b * T_ + t) * D_ + h * DH_;
    #pragma unroll
    for (int i = 0; i < 16; i++)
        *(float4*)(of + i * 4) = make_float4(o[i*4+0]*invl, o[i*4+1]*invl,
                                             o[i*4+2]*invl, o[i*4+3]*invl);
}

// ---------------- launch -----------------------------------------------------------
extern "C" void kernel_launch(void* const* d_in, const int* in_sizes, int n_in,
                              void* d_out, int out_size) {
    const float*        x     = (const float*)d_in[0];
    const unsigned int* mask  = (const unsigned int*)d_in[1];
    const float*        gamma = (const float*)d_in[2];
    const float*        beta  = (const float*)d_in[3];
    const float*        Wqkv  = (const float*)d_in[4];
    const float*        bqkv  = (const float*)d_in[5];
    const float*        Wout  = (const float*)d_in[6];
    const float*        bout  = (const float*)d_in[7];
    float* out = (float*)d_out;

    ln_kernel<<<M_, 256>>>(x, gamma, beta);
    rope_table_kernel<<<(T_ * HALF_D + 255) / 256, 256>>>();
    len_kernel<<<B_, 256>>>(mask);

    gemm_x2<N3_, true><<<dim3(N3_/128, M_/128), 256>>>(g_xn, Wqkv, bqkv, g_qkv);
    check_qkv_kernel<<<1, 256>>>(Wqkv, bqkv);
    gemm_fb_qkv<<<dim3(N3_/128, M_/128), 256>>>(Wqkv, bqkv);

    attn_x2<<<dim3(T_/256, B_*H_), 256>>>();
    check_attn_kernel<<<1, 256>>>();
    attn_fb<<<dim3(T_/256, B_*H_), 256>>>();

    gemm_x2<D_, false><<<dim3(D_/128, M_/128), 256>>>(g_attn, Wout, bout, out);
    check_out_kernel<<<1, 256>>>(Wout, bout, out);
    gemm_fb_out<<<dim3(D_/128, M_/128), 256>>>(Wout, bout, out);
}

// round 10
// speedup vs baseline: 5.7758x; 2.3357x over previous
#include <cuda_runtime.h>
#include <math.h>
#include <cstdint>

#define B_  8
#define T_  1024
#define D_  1024
#define H_  16
#define DH_ 64
#define M_  (B_*T_)     // 8192
#define N3_ (3*D_)      // 3072
#define HALF_D 512

// ---------------- scratch -------------------------------------------------------
__device__ __align__(1024) float g_xn[(size_t)M_*D_];
__device__ __align__(1024) float g_qkv[(size_t)M_*N3_];
__device__ __align__(1024) float g_attn[(size_t)M_*D_];
__device__ float g_sin[T_*HALF_D];      // [t][pair]
__device__ float g_cos[T_*HALF_D];
__device__ int   g_len[B_];
__device__ int   g_flag_a;              // 1 -> poly-exp attention wrong
__device__ int   g_flag_o;              // 1 -> prefetch out-proj wrong

// ---------------- fast exp on the FMA pipe (no MUFU), x <= 0 --------------------
__device__ __forceinline__ float fexp(float x) {
    x = fmaxf(x, -87.0f);
    const float y = x * 1.4426950408889634f;         // x * log2(e)
    const float n = rintf(y);
    const float t = (y - n) * 0.6931471805599453f;   // |t| <= 0.3466
    float p = fmaf(t, 1.0f/120.0f, 1.0f/24.0f);
    p = fmaf(t, p, 1.0f/6.0f);
    p = fmaf(t, p, 0.5f);
    p = fmaf(t, p, 1.0f);
    p = fmaf(t, p, 1.0f);
    const int e = (int)n;
    return p * __int_as_float((e + 127) << 23);
}

// ---------------- layernorm (round-1 exact) -------------------------------------
__global__ void __launch_bounds__(256) ln_kernel(const float* __restrict__ x,
                                                 const float* __restrict__ gamma,
                                                 const float* __restrict__ beta) {
    __shared__ float ssum[8], ssq[8];
    const int row = blockIdx.x;
    const int tid = threadIdx.x;
    float4 v = *(const float4*)(x + (size_t)row * D_ + tid * 4);
    float s = v.x + v.y + v.z + v.w;
    float q = v.x*v.x + v.y*v.y + v.z*v.z + v.w*v.w;
    #pragma unroll
    for (int o = 16; o > 0; o >>= 1) {
        s += __shfl_down_sync(0xffffffffu, s, o);
        q += __shfl_down_sync(0xffffffffu, q, o);
    }
    if ((tid & 31) == 0) { ssum[tid >> 5] = s; ssq[tid >> 5] = q; }
    __syncthreads();
    float ts = 0.f, tq = 0.f;
    #pragma unroll
    for (int i = 0; i < 8; i++) { ts += ssum[i]; tq += ssq[i]; }
    const float mu  = ts * (1.f / 1024.f);
    const float var = tq * (1.f / 1024.f) - mu * mu;
    const float inv = rsqrtf(var + 1e-5f);
    float4 g  = *(const float4*)(gamma + tid * 4);
    float4 be = *(const float4*)(beta  + tid * 4);
    float4 out;
    out.x = (v.x - mu) * inv * g.x + be.x;
    out.y = (v.y - mu) * inv * g.y + be.y;
    out.z = (v.z - mu) * inv * g.z + be.z;
    out.w = (v.w - mu) * inv * g.w + be.w;
    *(float4*)(g_xn + (size_t)row * D_ + tid * 4) = out;
}

// ---------------- rope tables (round-1 exact) ------------------------------------
__global__ void rope_table_kernel() {
    const int idx = blockIdx.x * blockDim.x + threadIdx.x;
    if (idx >= T_ * HALF_D) return;
    const int t = idx >> 9;
    const int i = idx & (HALF_D - 1);
    const float e   = -(((float)i - 1.0f) * (1.0f / 512.0f));
    const float inv = expf(e * 11.512925464970229f);   // ln(1e5)
    float sn, cs;
    sincosf((float)t * inv, &sn, &cs);
    g_sin[idx] = sn;
    g_cos[idx] = cs;
}

// ---------------- sequence lengths (round-1 exact) --------------------------------
__global__ void len_kernel(const unsigned int* __restrict__ mask) {
    __shared__ int sc[8];
    const int b = blockIdx.x, tid = threadIdx.x;
    int c = 0;
    for (int i = tid; i < T_; i += 256) c += (mask[b * T_ + i] != 0u);
    #pragma unroll
    for (int o = 16; o > 0; o >>= 1) c += __shfl_down_sync(0xffffffffu, c, o);
    if ((tid & 31) == 0) sc[tid >> 5] = c;
    __syncthreads();
    if (tid == 0) {
        int t = 0;
        #pragma unroll
        for (int i = 0; i < 8; i++) t += sc[i];
        g_len[b] = t;
    }
}

// ---------------- SGEMM 128x128x8, 8x8/thread (round-1 exact body) ----------------
template<int N, bool ROPE>
__device__ __forceinline__ void gemm_body(const float* __restrict__ A,
                                          const float* __restrict__ Bm,
                                          const float* __restrict__ bias,
                                          float* __restrict__ C) {
    __shared__ float As[8][128];
    __shared__ float Bs[8][128];
    const int tid = threadIdx.x;
    const int bm = blockIdx.y, bn = blockIdx.x;
    const int arow = tid >> 1, acol = (tid & 1) << 2;
    const int brow = tid >> 5, bcol = (tid & 31) << 2;
    const int tx = tid & 15, ty = tid >> 4;

    const float* Ap = A + (size_t)(bm * 128 + arow) * 1024 + acol;
    const float* Bp = Bm + (size_t)brow * N + bn * 128 + bcol;

    float acc[8][8];
    #pragma unroll
    for (int i = 0; i < 8; i++)
        #pragma unroll
        for (int j = 0; j < 8; j++) acc[i][j] = 0.f;

    for (int k0 = 0; k0 < 1024; k0 += 8) {
        float4 a4 = *(const float4*)(Ap + k0);
        float4 b4 = *(const float4*)(Bp + (size_t)k0 * N);
        As[acol + 0][arow] = a4.x;
        As[acol + 1][arow] = a4.y;
        As[acol + 2][arow] = a4.z;
        As[acol + 3][arow] = a4.w;
        *(float4*)(&Bs[brow][bcol]) = b4;
        __syncthreads();
        #pragma unroll
        for (int kk = 0; kk < 8; kk++) {
            float4 a0 = *(const float4*)(&As[kk][ty * 8]);
            float4 a1 = *(const float4*)(&As[kk][ty * 8 + 4]);
            float4 b0 = *(const float4*)(&Bs[kk][tx * 8]);
            float4 b1 = *(const float4*)(&Bs[kk][tx * 8 + 4]);
            float ar[8] = {a0.x, a0.y, a0.z, a0.w, a1.x, a1.y, a1.z, a1.w};
            float br[8] = {b0.x, b0.y, b0.z, b0.w, b1.x, b1.y, b1.z, b1.w};
            #pragma unroll
            for (int i = 0; i < 8; i++)
                #pragma unroll
                for (int j = 0; j < 8; j++)
                    acc[i][j] = fmaf(ar[i], br[j], acc[i][j]);
        }
        __syncthreads();
    }

    const int row0 = bm * 128 + ty * 8;
    const int col0 = bn * 128 + tx * 8;
    #pragma unroll
    for (int i = 0; i < 8; i++) {
        const int r = row0 + i;
        if (ROPE) {
            const int t = r & (T_ - 1);
            #pragma unroll
            for (int j = 0; j < 8; j += 2) {
                const int c  = col0 + j;
                const int pi = (c & (D_ - 1)) >> 1;
                const float sn = g_sin[t * HALF_D + pi];
                const float cs = g_cos[t * HALF_D + pi];
                const float e = acc[i][j]     + bias[c];
                const float o = acc[i][j + 1] + bias[c + 1];
                acc[i][j]     = fmaf(e, cs, -o * sn);
                acc[i][j + 1] = fmaf(o, cs,  e * sn);
            }
        } else {
            #pragma unroll
            for (int j = 0; j < 8; j++) acc[i][j] += bias[col0 + j];
        }
        float4* out = (float4*)(C + (size_t)r * N + col0);
        out[0] = make_float4(acc[i][0], acc[i][1], acc[i][2], acc[i][3]);
        out[1] = make_float4(acc[i][4], acc[i][5], acc[i][6], acc[i][7]);
    }
}

__global__ void __launch_bounds__(256) gemm_qkv_kernel(const float* __restrict__ Wqkv,
                                                       const float* __restrict__ bqkv) {
    gemm_body<N3_, true>(g_xn, Wqkv, bqkv, g_qkv);
}

// ---------------- out-proj: prefetch EXPERIMENT (check+fallback guarded) ----------
__global__ void __launch_bounds__(256) gemm_pf_out(const float* __restrict__ Bm,
                                                   const float* __restrict__ bias,
                                                   float* __restrict__ C) {
    __shared__ float As[8][128];
    __shared__ float Bs[8][128];
    const int tid = threadIdx.x;
    const int bm = blockIdx.y, bn = blockIdx.x;
    const int arow = tid >> 1, acol = (tid & 1) << 2;
    const int brow = tid >> 5, bcol = (tid & 31) << 2;
    const int tx = tid & 15, ty = tid >> 4;

    const float* Ap = g_attn + (size_t)(bm * 128 + arow) * 1024 + acol;
    const float* Bp = Bm + (size_t)brow * D_ + bn * 128 + bcol;

    float acc[8][8];
    #pragma unroll
    for (int i = 0; i < 8; i++)
        #pragma unroll
        for (int j = 0; j < 8; j++) acc[i][j] = 0.f;

    float4 a4 = *(const float4*)(Ap);
    float4 b4 = *(const float4*)(Bp);

    for (int k0 = 0; k0 < 1024; k0 += 8) {
        As[acol + 0][arow] = a4.x;
        As[acol + 1][arow] = a4.y;
        As[acol + 2][arow] = a4.z;
        As[acol + 3][arow] = a4.w;
        *(float4*)(&Bs[brow][bcol]) = b4;
        __syncthreads();
        if (k0 + 8 < 1024) {
            a4 = *(const float4*)(Ap + k0 + 8);
            b4 = *(const float4*)(Bp + (size_t)(k0 + 8) * D_);
        }
        #pragma unroll
        for (int kk = 0; kk < 8; kk++) {
            float4 a0 = *(const float4*)(&As[kk][ty * 8]);
            float4 a1 = *(const float4*)(&As[kk][ty * 8 + 4]);
            float4 b0 = *(const float4*)(&Bs[kk][tx * 8]);
            float4 b1 = *(const float4*)(&Bs[kk][tx * 8 + 4]);
            float ar[8] = {a0.x, a0.y, a0.z, a0.w, a1.x, a1.y, a1.z, a1.w};
            float br[8] = {b0.x, b0.y, b0.z, b0.w, b1.x, b1.y, b1.z, b1.w};
            #pragma unroll
            for (int i = 0; i < 8; i++)
                #pragma unroll
                for (int j = 0; j < 8; j++)
                    acc[i][j] = fmaf(ar[i], br[j], acc[i][j]);
        }
        __syncthreads();
    }

    const int row0 = bm * 128 + ty * 8;
    const int col0 = bn * 128 + tx * 8;
    #pragma unroll
    for (int i = 0; i < 8; i++) {
        const int r = row0 + i;
        #pragma unroll
        for (int j = 0; j < 8; j++) acc[i][j] += bias[col0 + j];
        float4* out = (float4*)(C + (size_t)r * D_ + col0);
        out[0] = make_float4(acc[i][0], acc[i][1], acc[i][2], acc[i][3]);
        out[1] = make_float4(acc[i][4], acc[i][5], acc[i][6], acc[i][7]);
    }
}

__global__ void __launch_bounds__(256) gemm_fb_out(const float* __restrict__ Wout,
                                                   const float* __restrict__ bout,
                                                   float* __restrict__ out) {
    if (g_flag_o == 0) return;
    gemm_body<D_, false>(g_attn, Wout, bout, out);
}

// ---------------- flash attention, poly-exp ---------------------------------------
__global__ void __launch_bounds__(256, 1) attn_kernel() {
    __shared__ float ks[32][64];
    __shared__ float vs[32][64];
    __shared__ float scr[32][256];

    const int bh = blockIdx.y;
    const int b = bh >> 4, h = bh & 15;
    const int tid = threadIdx.x;
    const int t = blockIdx.x * 256 + tid;
    const int len = g_len[b];

    const float* qrow = g_qkv + (size_t)(b * T_ + t) * N3_ + h * DH_;
    float q[64];
    #pragma unroll
    for (int i = 0; i < 16; i++) {
        float4 v4 = *(const float4*)(qrow + i * 4);
        q[i*4+0] = v4.x; q[i*4+1] = v4.y; q[i*4+2] = v4.z; q[i*4+3] = v4.w;
    }
    float o[64];
    #pragma unroll
    for (int d = 0; d < 64; d++) o[d] = 0.f;
    float m = -1e30f, l = 0.f;

    const float* kbase = g_qkv + (size_t)(b * T_) * N3_ + D_     + h * DH_;
    const float* vbase = g_qkv + (size_t)(b * T_) * N3_ + 2 * D_ + h * DH_;

    for (int s0 = 0; s0 < T_; s0 += 32) {
        if (s0 >= len) break;
        #pragma unroll
        for (int p = 0; p < 2; p++) {
            const int idx = tid * 2 + p;
            const int r = idx >> 4, c = (idx & 15) << 2;
            *(float4*)&ks[r][c] = *(const float4*)(kbase + (size_t)(s0 + r) * N3_ + c);
            *(float4*)&vs[r][c] = *(const float4*)(vbase + (size_t)(s0 + r) * N3_ + c);
        }
        __syncthreads();

        const int nv = min(32, len - s0);
        float tmax = -1e30f;
        for (int s = 0; s < 32; s++) {
            float acc = 0.f;
            #pragma unroll
            for (int d4 = 0; d4 < 16; d4++) {
                float4 kv = *(const float4*)&ks[s][d4 * 4];
                acc = fmaf(q[d4*4+0], kv.x, acc);
                acc = fmaf(q[d4*4+1], kv.y, acc);
                acc = fmaf(q[d4*4+2], kv.z, acc);
                acc = fmaf(q[d4*4+3], kv.w, acc);
            }
            acc *= 0.125f;
            scr[s][tid] = acc;
            if (s < nv) tmax = fmaxf(tmax, acc);
        }
        const float mnew = fmaxf(m, tmax);
        const float corr = fexp(m - mnew);
        l *= corr;
        #pragma unroll
        for (int d = 0; d < 64; d++) o[d] *= corr;
        for (int s = 0; s < nv; s++) {
            const float p = fexp(scr[s][tid] - mnew);
            l += p;
            #pragma unroll
            for (int d4 = 0; d4 < 16; d4++) {
                float4 vv = *(const float4*)&vs[s][d4 * 4];
                o[d4*4+0] = fmaf(p, vv.x, o[d4*4+0]);
                o[d4*4+1] = fmaf(p, vv.y, o[d4*4+1]);
                o[d4*4+2] = fmaf(p, vv.z, o[d4*4+2]);
                o[d4*4+3] = fmaf(p, vv.w, o[d4*4+3]);
            }
        }
        m = mnew;
        __syncthreads();
    }

    const float invl = 1.f / l;
    float* of = g_attn + (size_t)(b * T_ + t) * D_ + h * DH_;
    #pragma unroll
    for (int i = 0; i < 16; i++)
        *(float4*)(of + i * 4) = make_float4(o[i*4+0]*invl, o[i*4+1]*invl,
                                             o[i*4+2]*invl, o[i*4+3]*invl);
}

// ---------------- attention check (expf reference vs g_attn) ----------------------
__global__ void __launch_bounds__(256) check_attn_kernel() {
    __shared__ int bad;
    const int tid = threadIdx.x, lane = tid & 31, w = tid >> 5;
    if (tid == 0) bad = 0;
    __syncthreads();
    const int b = w;
    const int h = (w * 5) & 15;
    const int t = (w * 373 + 29) & (T_ - 1);
    const int len = g_len[b];
    const float* qrow = g_qkv + (size_t)(b*T_ + t)*N3_ + h*DH_;
    float q[64];
    for (int i = 0; i < 64; i++) q[i] = qrow[i];
    float arr[32];
    const int nj = (len + 31) >> 5;
    float mmax = -1e30f;
    for (int j = 0; j < nj; j++) {
        const int s = lane + 32*j;
        float sc = -1e30f;
        if (s < len) {
            const float* kr = g_qkv + (size_t)(b*T_ + s)*N3_ + D_ + h*DH_;
            float acc = 0.f;
            for (int d = 0; d < 64; d++) acc = fmaf(q[d], kr[d], acc);
            sc = acc * 0.125f;
            mmax = fmaxf(mmax, sc);
        }
        arr[j] = sc;
    }
    #pragma unroll
    for (int o = 16; o > 0; o >>= 1)
        mmax = fmaxf(mmax, __shfl_xor_sync(0xffffffffu, mmax, o));
    float l = 0.f;
    for (int j = 0; j < nj; j++) {
        const int s = lane + 32*j;
        arr[j] = (s < len) ? expf(arr[j] - mmax) : 0.f;
        l += arr[j];
    }
    #pragma unroll
    for (int o = 16; o > 0; o >>= 1) l += __shfl_xor_sync(0xffffffffu, l, o);
    const float invl = 1.f / l;
    for (int d = 0; d < 64; d++) {
        float acc = 0.f;
        for (int j = 0; j < nj; j++) {
            const int s = lane + 32*j;
            if (s < len)
                acc = fmaf(arr[j],
                           g_qkv[(size_t)(b*T_+s)*N3_ + 2*D_ + h*DH_ + d], acc);
        }
        #pragma unroll
        for (int o = 16; o > 0; o >>= 1) acc += __shfl_xor_sync(0xffffffffu, acc, o);
        if (lane == 0) {
            const float ref = acc * invl;
            const float got = g_attn[(size_t)(b*T_+t)*D_ + h*DH_ + d];
            if (fabsf(got - ref) > 0.01f + 0.01f * fabsf(ref)) bad = 1;
        }
    }
    __syncthreads();
    if (tid == 0) g_flag_a = bad;
}

// ---------------- attention fallback (round-1 expf), flag-gated -------------------
__global__ void __launch_bounds__(256, 1) attn_fb() {
    if (g_flag_a == 0) return;
    __shared__ float ks[32][64];
    __shared__ float vs[32][64];
    __shared__ float scr[32][256];

    const int bh = blockIdx.y;
    const int b = bh >> 4, h = bh & 15;
    const int tid = threadIdx.x;
    const int t = blockIdx.x * 256 + tid;
    const int len = g_len[b];

    const float* qrow = g_qkv + (size_t)(b * T_ + t) * N3_ + h * DH_;
    float q[64];
    #pragma unroll
    for (int i = 0; i < 16; i++) {
        float4 v4 = *(const float4*)(qrow + i * 4);
        q[i*4+0] = v4.x; q[i*4+1] = v4.y; q[i*4+2] = v4.z; q[i*4+3] = v4.w;
    }
    float o[64];
    #pragma unroll
    for (int d = 0; d < 64; d++) o[d] = 0.f;
    float m = -1e30f, l = 0.f;

    const float* kbase = g_qkv + (size_t)(b * T_) * N3_ + D_     + h * DH_;
    const float* vbase = g_qkv + (size_t)(b * T_) * N3_ + 2 * D_ + h * DH_;

    for (int s0 = 0; s0 < T_; s0 += 32) {
        if (s0 >= len) break;
        #pragma unroll
        for (int p = 0; p < 2; p++) {
            const int idx = tid * 2 + p;
            const int r = idx >> 4, c = (idx & 15) << 2;
            *(float4*)&ks[r][c] = *(const float4*)(kbase + (size_t)(s0 + r) * N3_ + c);
            *(float4*)&vs[r][c] = *(const float4*)(vbase + (size_t)(s0 + r) * N3_ + c);
        }
        __syncthreads();

        const int nv = min(32, len - s0);
        float tmax = -1e30f;
        for (int s = 0; s < 32; s++) {
            float acc = 0.f;
            #pragma unroll
            for (int d4 = 0; d4 < 16; d4++) {
                float4 kv = *(const float4*)&ks[s][d4 * 4];
                acc = fmaf(q[d4*4+0], kv.x, acc);
                acc = fmaf(q[d4*4+1], kv.y, acc);
                acc = fmaf(q[d4*4+2], kv.z, acc);
                acc = fmaf(q[d4*4+3], kv.w, acc);
            }
            acc *= 0.125f;
            scr[s][tid] = acc;
            if (s < nv) tmax = fmaxf(tmax, acc);
        }
        const float mnew = fmaxf(m, tmax);
        const float corr = expf(m - mnew);
        l *= corr;
        #pragma unroll
        for (int d = 0; d < 64; d++) o[d] *= corr;
        for (int s = 0; s < nv; s++) {
            const float p = expf(scr[s][tid] - mnew);
            l += p;
            #pragma unroll
            for (int d4 = 0; d4 < 16; d4++) {
                float4 vv = *(const float4*)&vs[s][d4 * 4];
                o[d4*4+0] = fmaf(p, vv.x, o[d4*4+0]);
                o[d4*4+1] = fmaf(p, vv.y, o[d4*4+1]);
                o[d4*4+2] = fmaf(p, vv.z, o[d4*4+2]);
                o[d4*4+3] = fmaf(p, vv.w, o[d4*4+3]);
            }
        }
        m = mnew;
        __syncthreads();
    }

    const float invl = 1.f / l;
    float* of = g_attn + (size_t)(b * T_ + t) * D_ + h * DH_;
    #pragma unroll
    for (int i = 0; i < 16; i++)
        *(float4*)(of + i * 4) = make_float4(o[i*4+0]*invl, o[i*4+1]*invl,
                                             o[i*4+2]*invl, o[i*4+3]*invl);
}

// ---------------- out-proj check (reference from trusted g_attn) ------------------
__global__ void __launch_bounds__(256) check_out_kernel(
    const float* __restrict__ W, const float* __restrict__ bias,
    const float* __restrict__ out) {
    __shared__ int bad;
    const int tid = threadIdx.x, lane = tid & 31, w = tid >> 5;
    if (tid == 0) bad = 0;
    __syncthreads();
    const int row = (w * 1237 + 17) & (M_ - 1);
    const int c0  = ((w * 677) % (D_ / 64)) * 64;
    const int ce  = c0 + lane * 2;
    const float* ar = g_attn + (size_t)row * D_;
    float se = 0.f, so = 0.f;
    for (int k = 0; k < D_; k++) {
        const float av = ar[k];
        se = fmaf(av, W[(size_t)k * D_ + ce],     se);
        so = fmaf(av, W[(size_t)k * D_ + ce + 1], so);
    }
    se += bias[ce]; so += bias[ce + 1];
    const float ge = out[(size_t)row * D_ + ce];
    const float go = out[(size_t)row * D_ + ce + 1];
    if (fabsf(ge - se) > 0.01f + 0.003f * fabsf(se) ||
        fabsf(go - so) > 0.01f + 0.003f * fabsf(so)) bad = 1;
    __syncthreads();
    if (tid == 0) g_flag_o = bad;
}

// ---------------- launch -----------------------------------------------------------
extern "C" void kernel_launch(void* const* d_in, const int* in_sizes, int n_in,
                              void* d_out, int out_size) {
    const float*        x     = (const float*)d_in[0];
    const unsigned int* mask  = (const unsigned int*)d_in[1];
    const float*        gamma = (const float*)d_in[2];
    const float*        beta  = (const float*)d_in[3];
    const float*        Wqkv  = (const float*)d_in[4];
    const float*        bqkv  = (const float*)d_in[5];
    const float*        Wout  = (const float*)d_in[6];
    const float*        bout  = (const float*)d_in[7];
    float* out = (float*)d_out;

    ln_kernel<<<M_, 256>>>(x, gamma, beta);
    rope_table_kernel<<<(T_ * HALF_D + 255) / 256, 256>>>();
    len_kernel<<<B_, 256>>>(mask);

    // QKV: trusted round-1 kernel, unmodified
    gemm_qkv_kernel<<<dim3(N3_/128, M_/128), 256>>>(Wqkv, bqkv);

    // attention: poly-exp attempt -> check -> flag-gated expf fallback
    attn_kernel<<<dim3(T_/256, B_*H_), 256>>>();
    check_attn_kernel<<<1, 256>>>();
    attn_fb<<<dim3(T_/256, B_*H_), 256>>>();

    // out-proj: prefetch experiment -> check -> flag-gated round-1 fallback
    gemm_pf_out<<<dim3(D_/128, M_/128), 256>>>(Wout, bout, out);
    check_out_kernel<<<1, 256>>>(Wout, bout, out);
    gemm_fb_out<<<dim3(D_/128, M_/128), 256>>>(Wout, bout, out);
}